// round 11
// baseline (speedup 1.0000x reference)
#include <cuda_runtime.h>
#include <cuda_fp16.h>
#include <math.h>
#include <stdint.h>

// ---------------- problem constants ----------------
#define L_  6
#define B_  2
#define T_  1024
#define C_  768
#define H_  12
#define D_  64
#define F_  3072
#define V_  50257
#define VP_ 50304              // V padded to /128
#define M_  (B_ * T_)          // 2048 rows
#define EPS_ 1e-5f

// ---------------- scratch (device globals, no runtime alloc) ----------------
__device__ float  g_x    [M_ * C_];     // residual stream (fp32)
__device__ __half g_qkv16[M_ * 3 * C_]; // qkv (fp16)

// single-plane fp16 activations
__device__ __half g_ln16 [M_ * C_];
__device__ __half g_att16[M_ * C_];
__device__ __half g_mid16[M_ * F_];

// weight planes, converted once per replay
__device__ __half g_qkvw_h[L_ * C_ * 3 * C_];                       // 1-term
__device__ __half g_projw_h[L_ * C_ * C_], g_projw_l[L_ * C_ * C_]; // 2-term
__device__ __half g_w1_h  [L_ * C_ * F_];                           // 1-term
__device__ __half g_w2_h  [L_ * F_ * C_], g_w2_l  [L_ * F_ * C_];   // 2-term
__device__ __half g_hw_h  [C_ * VP_];                               // 1-term

// ---------------- helpers ----------------
__device__ __forceinline__ uint32_t smem_u32(const void* p) {
    uint32_t a;
    asm("{ .reg .u64 t; cvta.to.shared.u64 t, %1; cvt.u32.u64 %0, t; }" : "=r"(a) : "l"(p));
    return a;
}
__device__ __forceinline__ void cp16(uint32_t dst, const void* src) {
    asm volatile("cp.async.cg.shared.global [%0], [%1], 16;" :: "r"(dst), "l"(src));
}
__device__ __forceinline__ void cp_commit() {
    asm volatile("cp.async.commit_group;" ::: "memory");
}
__device__ __forceinline__ void ldsm_x4(uint32_t* r, uint32_t a) {
    asm volatile("ldmatrix.sync.aligned.m8n8.x4.shared.b16 {%0,%1,%2,%3}, [%4];"
        : "=r"(r[0]), "=r"(r[1]), "=r"(r[2]), "=r"(r[3]) : "r"(a));
}
__device__ __forceinline__ void ldsm_x2(uint32_t* r, uint32_t a) {
    asm volatile("ldmatrix.sync.aligned.m8n8.x2.shared.b16 {%0,%1}, [%2];"
        : "=r"(r[0]), "=r"(r[1]) : "r"(a));
}
__device__ __forceinline__ void ldsm_x2t(uint32_t* r, uint32_t a) {
    asm volatile("ldmatrix.sync.aligned.m8n8.x2.trans.shared.b16 {%0,%1}, [%2];"
        : "=r"(r[0]), "=r"(r[1]) : "r"(a));
}
__device__ __forceinline__ void mma_f16(float* d, const uint32_t* a, const uint32_t* b) {
    asm volatile("mma.sync.aligned.m16n8k16.row.col.f32.f16.f16.f32 "
        "{%0,%1,%2,%3}, {%4,%5,%6,%7}, {%8,%9}, {%0,%1,%2,%3};"
        : "+f"(d[0]), "+f"(d[1]), "+f"(d[2]), "+f"(d[3])
        : "r"(a[0]), "r"(a[1]), "r"(a[2]), "r"(a[3]), "r"(b[0]), "r"(b[1]));
}
__device__ __forceinline__ uint32_t packh2(float a, float b) {
    __half2 t = __floats2half2_rn(a, b);
    return *(uint32_t*)&t;
}
__device__ __forceinline__ void split1h(float x, __half& h, __half& l) {
    h = __float2half_rn(x);
    l = __float2half_rn(x - __half2float(h));
}
__device__ __forceinline__ float gelu_exact(float v) {
    return 0.5f * v * (1.0f + erff(v * 0.70710678118654752f));
}

// ---------------- weight conversion ----------------
__global__ void convert_kernel(const float* __restrict__ src,
                               __half* __restrict__ hi,
                               __half* __restrict__ lo, int n8) {
    int e = blockIdx.x * blockDim.x + threadIdx.x;
    if (e >= n8) return;
    #pragma unroll
    for (int q = 0; q < 2; q++) {
        size_t o4 = (size_t)e * 8 + q * 4;
        float4 v = *(const float4*)(src + o4);
        __half h[4], l[4];
        split1h(v.x, h[0], l[0]); split1h(v.y, h[1], l[1]);
        split1h(v.z, h[2], l[2]); split1h(v.w, h[3], l[3]);
        *(__half2*)(hi + o4)     = *(__half2*)&h[0];
        *(__half2*)(hi + o4 + 2) = *(__half2*)&h[2];
        *(__half2*)(lo + o4)     = *(__half2*)&l[0];
        *(__half2*)(lo + o4 + 2) = *(__half2*)&l[2];
    }
}

__global__ void convert_hi_kernel(const float* __restrict__ src,
                                  __half* __restrict__ hi, int n8) {
    int e = blockIdx.x * blockDim.x + threadIdx.x;
    if (e >= n8) return;
    #pragma unroll
    for (int q = 0; q < 2; q++) {
        size_t o4 = (size_t)e * 8 + q * 4;
        float4 v = *(const float4*)(src + o4);
        __half h[4];
        h[0] = __float2half_rn(v.x); h[1] = __float2half_rn(v.y);
        h[2] = __float2half_rn(v.z); h[3] = __float2half_rn(v.w);
        *(__half2*)(hi + o4)     = *(__half2*)&h[0];
        *(__half2*)(hi + o4 + 2) = *(__half2*)&h[2];
    }
}

// head_w [C_ x V_] -> padded single fp16 plane [C_ x VP_]
__global__ void convert_head_kernel(const float* __restrict__ src,
                                    __half* __restrict__ hi) {
    int e = blockIdx.x * blockDim.x + threadIdx.x;
    if (e >= C_ * (VP_ / 4)) return;
    int row = e / (VP_ / 4);
    int c0  = (e % (VP_ / 4)) * 4;
    __half h[4];
    #pragma unroll
    for (int j = 0; j < 4; j++) {
        int c = c0 + j;
        h[j] = __float2half_rn((c < V_) ? src[(size_t)row * V_ + c] : 0.0f);
    }
    size_t o = (size_t)row * VP_ + c0;
    *(__half2*)(hi + o)     = *(__half2*)&h[0];
    *(__half2*)(hi + o + 2) = *(__half2*)&h[2];
}

// ---------------- embedding ----------------
__global__ void embed_kernel(const int* __restrict__ idx,
                             const float* __restrict__ wte,
                             const float* __restrict__ pte,
                             float* __restrict__ x) {
    int r = blockIdx.x;
    int t = r % T_;
    int tok = idx[r];
    const float* wrow = wte + (size_t)tok * C_;
    const float* prow = pte + (size_t)t * C_;
    float* xr = x + (size_t)r * C_;
    for (int c = threadIdx.x; c < C_; c += blockDim.x)
        xr[c] = wrow[c] + prow[c];
}

// ---------------- layernorm: warp per row, shuffle reduce -> fp16 ----------------
// grid M_/8, block 256 (8 warps)
__global__ __launch_bounds__(256) void layernorm_kernel(
        const float* __restrict__ x,
        const float* __restrict__ sc,
        const float* __restrict__ bi,
        __half* __restrict__ y) {
    int w = threadIdx.x >> 5, lane = threadIdx.x & 31;
    int r = blockIdx.x * 8 + w;
    const float* xr = x + (size_t)r * C_;
    float v[24];
    float s = 0.0f, ss = 0.0f;
    #pragma unroll
    for (int i = 0; i < 6; i++) {
        float4 t = *(const float4*)(xr + (i * 32 + lane) * 4);
        v[i*4+0] = t.x; v[i*4+1] = t.y; v[i*4+2] = t.z; v[i*4+3] = t.w;
        s  += t.x + t.y + t.z + t.w;
        ss += t.x*t.x + t.y*t.y + t.z*t.z + t.w*t.w;
    }
    #pragma unroll
    for (int off = 16; off > 0; off >>= 1) {
        s  += __shfl_xor_sync(0xffffffff, s, off);
        ss += __shfl_xor_sync(0xffffffff, ss, off);
    }
    float mu   = s * (1.0f / C_);
    float var  = ss * (1.0f / C_) - mu * mu;
    float rstd = rsqrtf(var + EPS_);
    size_t base = (size_t)r * C_;
    #pragma unroll
    for (int i = 0; i < 6; i++) {
        int col = (i * 32 + lane) * 4;
        float4 scv = *(const float4*)(sc + col);
        float4 biv = *(const float4*)(bi + col);
        __half h[4];
        h[0] = __float2half_rn((v[i*4+0] - mu) * rstd * scv.x + biv.x);
        h[1] = __float2half_rn((v[i*4+1] - mu) * rstd * scv.y + biv.y);
        h[2] = __float2half_rn((v[i*4+2] - mu) * rstd * scv.z + biv.z);
        h[3] = __float2half_rn((v[i*4+3] - mu) * rstd * scv.w + biv.w);
        *(uint2*)(y + base + col) = *(uint2*)&h[0];
    }
}

// ---------------- FA2-style block attention, fp16 qkv, cp.async tiles ----------------
__global__ __launch_bounds__(128) void attn_kernel(const __half* __restrict__ qkv,
                                                   __half* __restrict__ o16) {
    __shared__ __align__(1024) __half sQ[64 * 64];
    __shared__ __align__(1024) __half sK[64 * 64];
    __shared__ __align__(1024) __half sV[64 * 64];
    uint32_t qB = smem_u32(sQ), kB = smem_u32(sK), vB = smem_u32(sV);
    int tid = threadIdx.x, lane = tid & 31, wid = tid >> 5;
    int q0 = blockIdx.x * 64;
    int bh = blockIdx.y;
    int b = bh / H_, h = bh % H_;
    const __half* base = qkv + (size_t)b * T_ * 3 * C_ + h * D_;

    #pragma unroll
    for (int i = 0; i < 4; i++) {
        int e = tid + 128 * i;
        int r = e >> 3, u = e & 7;
        uint32_t d = qB + (uint32_t)(r * 128 + ((u ^ (r & 7)) << 4));
        cp16(d, base + (size_t)(q0 + r) * 3 * C_ + u * 8);
    }
    cp_commit();
    asm volatile("cp.async.wait_group 0;" ::: "memory");
    __syncthreads();

    uint32_t qa[4][4];
    #pragma unroll
    for (int ks = 0; ks < 4; ks++) {
        int r = wid * 16 + (lane & 15);
        int c = ks * 2 + (lane >> 4);
        ldsm_x4(qa[ks], qB + (uint32_t)(r * 128 + ((c ^ (r & 7)) << 4)));
    }

    float m1 = -1e30f, m2 = -1e30f, l1 = 0.0f, l2 = 0.0f;
    float oacc[8][4];
    #pragma unroll
    for (int dt = 0; dt < 8; dt++)
        #pragma unroll
        for (int i = 0; i < 4; i++) oacc[dt][i] = 0.0f;

    int r1loc = wid * 16 + (lane >> 2);

    for (int j0 = 0; j0 <= q0; j0 += 64) {
        __syncthreads();
        #pragma unroll
        for (int i = 0; i < 4; i++) {
            int e = tid + 128 * i;
            int r = e >> 3, u = e & 7;
            uint32_t off = (uint32_t)(r * 128 + ((u ^ (r & 7)) << 4));
            cp16(kB + off, base + C_     + (size_t)(j0 + r) * 3 * C_ + u * 8);
            cp16(vB + off, base + 2 * C_ + (size_t)(j0 + r) * 3 * C_ + u * 8);
        }
        cp_commit();
        asm volatile("cp.async.wait_group 0;" ::: "memory");
        __syncthreads();

        float sc[8][4];
        #pragma unroll
        for (int nt = 0; nt < 8; nt++)
            #pragma unroll
            for (int i = 0; i < 4; i++) sc[nt][i] = 0.0f;
        #pragma unroll
        for (int ks = 0; ks < 4; ks++) {
            #pragma unroll
            for (int nt = 0; nt < 8; nt++) {
                int n = nt * 8 + (lane & 7);
                int g = ks * 2 + ((lane >> 3) & 1);
                uint32_t kb[2];
                ldsm_x2(kb, kB + (uint32_t)(n * 128 + ((g ^ (n & 7)) << 4)));
                mma_f16(sc[nt], qa[ks], kb);
            }
        }
        #pragma unroll
        for (int nt = 0; nt < 8; nt++)
            #pragma unroll
            for (int i = 0; i < 4; i++) sc[nt][i] *= 0.125f;

        if (j0 == q0) {
            #pragma unroll
            for (int nt = 0; nt < 8; nt++) {
                int cb = nt * 8 + (lane & 3) * 2;
                if (cb     > r1loc) sc[nt][0] = -1e30f;
                if (cb + 1 > r1loc) sc[nt][1] = -1e30f;
                if (cb     > r1loc + 8) sc[nt][2] = -1e30f;
                if (cb + 1 > r1loc + 8) sc[nt][3] = -1e30f;
            }
        }

        float nm1 = m1, nm2 = m2;
        #pragma unroll
        for (int nt = 0; nt < 8; nt++) {
            nm1 = fmaxf(nm1, fmaxf(sc[nt][0], sc[nt][1]));
            nm2 = fmaxf(nm2, fmaxf(sc[nt][2], sc[nt][3]));
        }
        #pragma unroll
        for (int o = 1; o <= 2; o <<= 1) {
            nm1 = fmaxf(nm1, __shfl_xor_sync(0xffffffff, nm1, o));
            nm2 = fmaxf(nm2, __shfl_xor_sync(0xffffffff, nm2, o));
        }
        float corr1 = __expf(m1 - nm1);
        float corr2 = __expf(m2 - nm2);
        m1 = nm1; m2 = nm2;
        float rs1 = 0.0f, rs2 = 0.0f;
        #pragma unroll
        for (int nt = 0; nt < 8; nt++) {
            sc[nt][0] = __expf(sc[nt][0] - m1);
            sc[nt][1] = __expf(sc[nt][1] - m1);
            sc[nt][2] = __expf(sc[nt][2] - m2);
            sc[nt][3] = __expf(sc[nt][3] - m2);
            rs1 += sc[nt][0] + sc[nt][1];
            rs2 += sc[nt][2] + sc[nt][3];
        }
        #pragma unroll
        for (int o = 1; o <= 2; o <<= 1) {
            rs1 += __shfl_xor_sync(0xffffffff, rs1, o);
            rs2 += __shfl_xor_sync(0xffffffff, rs2, o);
        }
        l1 = l1 * corr1 + rs1;
        l2 = l2 * corr2 + rs2;
        #pragma unroll
        for (int dt = 0; dt < 8; dt++) {
            oacc[dt][0] *= corr1; oacc[dt][1] *= corr1;
            oacc[dt][2] *= corr2; oacc[dt][3] *= corr2;
        }

        #pragma unroll
        for (int ks = 0; ks < 4; ks++) {
            uint32_t pa[4];
            pa[0] = packh2(sc[2 * ks][0],     sc[2 * ks][1]);
            pa[1] = packh2(sc[2 * ks][2],     sc[2 * ks][3]);
            pa[2] = packh2(sc[2 * ks + 1][0], sc[2 * ks + 1][1]);
            pa[3] = packh2(sc[2 * ks + 1][2], sc[2 * ks + 1][3]);
            #pragma unroll
            for (int dt = 0; dt < 8; dt++) {
                int kt = ks * 16 + (lane & 15);
                uint32_t vb[2];
                ldsm_x2t(vb, vB + (uint32_t)(kt * 128 + ((dt ^ (kt & 7)) << 4)));
                mma_f16(oacc[dt], pa, vb);
            }
        }
    }

    float inv1 = 1.0f / l1, inv2 = 1.0f / l2;
    int rowg = b * T_ + q0 + r1loc;
    #pragma unroll
    for (int dt = 0; dt < 8; dt++) {
        int col = h * D_ + dt * 8 + (lane & 3) * 2;
        *(__half2*)(o16 + (size_t)rowg * C_ + col) =
            __floats2half2_rn(oacc[dt][0] * inv1, oacc[dt][1] * inv1);
        *(__half2*)(o16 + (size_t)(rowg + 8) * C_ + col) =
            __floats2half2_rn(oacc[dt][2] * inv2, oacc[dt][3] * inv2);
    }
}

// ================= fp16 GEMM: C = A*(Bh[+Bl]), 3-stage cp.async =================
// Tile BM x 128, BK=64, 256 threads.
template<int HAS_BIAS, int DO_GELU, int DO_RES, int WRITE_F16, int TERMS, int BM>
__global__ __launch_bounds__(256, 1) void tc_gemm(
        const __half* __restrict__ Af,
        const __half* __restrict__ Bhi, const __half* __restrict__ Blo,
        const float* __restrict__ bias, const float* __restrict__ res,
        float* __restrict__ Cf, __half* __restrict__ C16,
        int M, int Nb, int Nc, int K) {
    constexpr int MT = BM / 32;                        // m-tiles per warp
    constexpr uint32_t ABYTES = (uint32_t)BM * 128;    // A stage bytes
    constexpr uint32_t STGB = ABYTES + ((TERMS == 2) ? 32768u : 16384u);
    extern __shared__ __align__(1024) char dsm[];
    uint32_t sb = smem_u32(dsm);
    const int tid = threadIdx.x, lane = tid & 31, wid = tid >> 5;
    const int wm = wid >> 2, wn = wid & 3;
    const int m0 = blockIdx.x * BM, n0 = blockIdx.y * 128;
    const int niter = K >> 6;

    float acc[MT][4][4];
    #pragma unroll
    for (int a = 0; a < MT; a++)
        #pragma unroll
        for (int b = 0; b < 4; b++)
            #pragma unroll
            for (int c = 0; c < 4; c++) acc[a][b][c] = 0.0f;

    auto PREFETCH = [&](int it) {
        if (it < niter) {
            int k0 = it << 6;
            uint32_t buf = sb + (it % 3) * STGB;
            #pragma unroll
            for (int i = 0; i < BM / 32; i++) {
                int e = tid + 256 * i;
                int r = e >> 3, u = e & 7;
                uint32_t d = buf + (uint32_t)(r * 128 + ((u ^ (r & 7)) << 4));
                cp16(d, Af + (size_t)(m0 + r) * K + k0 + u * 8);
            }
            #pragma unroll
            for (int i = 0; i < 4; i++) {
                int e = tid + 256 * i;
                int kr = e >> 4, u = e & 15;
                uint32_t d = buf + ABYTES + (uint32_t)(kr * 256 + ((u ^ (kr & 7)) << 4));
                size_t so = (size_t)(k0 + kr) * Nb + n0 + u * 8;
                cp16(d, Bhi + so);
                if (TERMS == 2) cp16(d + 16384, Blo + so);
            }
        }
        cp_commit();
    };

    auto COMPUTE = [&](int stg) {
        uint32_t aBase = sb + stg * STGB;
        uint32_t bBase = aBase + ABYTES;
        #pragma unroll
        for (int ks = 0; ks < 4; ks++) {
            uint32_t af[MT][4];
            #pragma unroll
            for (int mt = 0; mt < MT; mt++) {
                int r = wm * (BM / 2) + mt * 16 + (lane & 15);
                int c = ks * 2 + (lane >> 4);
                uint32_t off = (uint32_t)(r * 128 + ((c ^ (r & 7)) << 4));
                ldsm_x4(af[mt], aBase + off);
            }
            uint32_t bh[4][2], blr[4][2];
            #pragma unroll
            for (int nt = 0; nt < 4; nt++) {
                int kt = ks * 16 + (lane & 15);
                int c = wn * 4 + nt;
                uint32_t off = (uint32_t)(kt * 256 + ((c ^ (kt & 7)) << 4));
                ldsm_x2t(bh[nt],  bBase + off);
                if (TERMS == 2) ldsm_x2t(blr[nt], bBase + 16384 + off);
            }
            #pragma unroll
            for (int mt = 0; mt < MT; mt++)
                #pragma unroll
                for (int nt = 0; nt < 4; nt++) {
                    mma_f16(acc[mt][nt], af[mt], bh[nt]);
                    if (TERMS == 2) mma_f16(acc[mt][nt], af[mt], blr[nt]);
                }
        }
    };

    PREFETCH(0);
    PREFETCH(1);
    for (int it = 0; it < niter; it++) {
        asm volatile("cp.async.wait_group 1;" ::: "memory");
        __syncthreads();
        COMPUTE(it % 3);
        PREFETCH(it + 2);
    }

    #pragma unroll
    for (int mt = 0; mt < MT; mt++) {
        int r0 = m0 + wm * (BM / 2) + mt * 16 + (lane >> 2);
        #pragma unroll
        for (int nt = 0; nt < 4; nt++) {
            int c0 = n0 + wn * 32 + nt * 8 + (lane & 3) * 2;
            float v[4];
            #pragma unroll
            for (int i = 0; i < 4; i++) {
                v[i] = acc[mt][nt][i];
                int col = c0 + (i & 1);
                if (HAS_BIAS && col < Nc) v[i] += bias[col];
                if (DO_GELU) v[i] = gelu_exact(v[i]);
            }
            if (WRITE_F16) {
                #pragma unroll
                for (int half_i = 0; half_i < 2; half_i++) {
                    int row = r0 + half_i * 8;
                    size_t o = (size_t)row * Nc + c0;
                    *(__half2*)(C16 + o) =
                        __floats2half2_rn(v[half_i * 2], v[half_i * 2 + 1]);
                }
            } else {
                #pragma unroll
                for (int i = 0; i < 4; i++) {
                    int row = r0 + (i >> 1) * 8;
                    int col = c0 + (i & 1);
                    if (col < Nc) {
                        float w = v[i];
                        if (DO_RES) w += res[(size_t)row * Nc + col];
                        Cf[(size_t)row * Nc + col] = w;
                    }
                }
            }
        }
    }
}

#define SM_1T128 (3 * 32768)   // 1-term, BM=128
#define SM_2T64  (3 * 40960)   // 2-term, BM=64

// ---------------- launch ----------------
extern "C" void kernel_launch(void* const* d_in, const int* in_sizes, int n_in,
                              void* d_out, int out_size) {
    const int*   idx    = (const int*)  d_in[0];
    const float* wte    = (const float*)d_in[1];
    const float* pte    = (const float*)d_in[2];
    const float* ln1_s  = (const float*)d_in[3];
    const float* ln1_b  = (const float*)d_in[4];
    const float* qkv_w  = (const float*)d_in[5];
    const float* qkv_b  = (const float*)d_in[6];
    const float* proj_w = (const float*)d_in[7];
    const float* proj_b = (const float*)d_in[8];
    const float* ln2_s  = (const float*)d_in[9];
    const float* ln2_b  = (const float*)d_in[10];
    const float* w1     = (const float*)d_in[11];
    const float* b1     = (const float*)d_in[12];
    const float* w2     = (const float*)d_in[13];
    const float* b2     = (const float*)d_in[14];
    const float* lnf_s  = (const float*)d_in[15];
    const float* lnf_b  = (const float*)d_in[16];
    const float* head_w = (const float*)d_in[17];
    float* out = (float*)d_out;

    float* px;
    cudaGetSymbolAddress((void**)&px, g_x);
    __half *qkv16, *ln16, *att16, *mid16;
    cudaGetSymbolAddress((void**)&qkv16, g_qkv16);
    cudaGetSymbolAddress((void**)&ln16,  g_ln16);
    cudaGetSymbolAddress((void**)&att16, g_att16);
    cudaGetSymbolAddress((void**)&mid16, g_mid16);
    __half *qwh, *pwh, *pwl, *w1h, *w2h, *w2l, *hwh;
    cudaGetSymbolAddress((void**)&qwh, g_qkvw_h);
    cudaGetSymbolAddress((void**)&pwh, g_projw_h); cudaGetSymbolAddress((void**)&pwl, g_projw_l);
    cudaGetSymbolAddress((void**)&w1h, g_w1_h);
    cudaGetSymbolAddress((void**)&w2h, g_w2_h);   cudaGetSymbolAddress((void**)&w2l, g_w2_l);
    cudaGetSymbolAddress((void**)&hwh, g_hw_h);

    cudaFuncSetAttribute(tc_gemm<1,0,0,1,1,128>, cudaFuncAttributeMaxDynamicSharedMemorySize, SM_1T128);
    cudaFuncSetAttribute(tc_gemm<1,0,1,0,2,64>,  cudaFuncAttributeMaxDynamicSharedMemorySize, SM_2T64);
    cudaFuncSetAttribute(tc_gemm<1,1,0,1,1,128>, cudaFuncAttributeMaxDynamicSharedMemorySize, SM_1T128);
    cudaFuncSetAttribute(tc_gemm<0,0,0,0,1,128>, cudaFuncAttributeMaxDynamicSharedMemorySize, SM_1T128);

    // ---- weight conversion (once per replay) ----
    {
        int n;
        n = L_ * C_ * 3 * C_ / 8;
        convert_hi_kernel<<<(n + 255) / 256, 256>>>(qkv_w, qwh, n);
        n = L_ * C_ * C_ / 8;
        convert_kernel<<<(n + 255) / 256, 256>>>(proj_w, pwh, pwl, n);
        n = L_ * C_ * F_ / 8;
        convert_hi_kernel<<<(n + 255) / 256, 256>>>(w1, w1h, n);
        n = L_ * F_ * C_ / 8;
        convert_kernel<<<(n + 255) / 256, 256>>>(w2, w2h, w2l, n);
        n = C_ * VP_ / 4;
        convert_head_kernel<<<(n + 255) / 256, 256>>>(head_w, hwh);
    }

    embed_kernel<<<M_, 256>>>(idx, wte, pte, px);

    for (int l = 0; l < L_; l++) {
        const __half* qwh_l = qwh + (size_t)l * C_ * 3 * C_;
        const __half* pwh_l = pwh + (size_t)l * C_ * C_;
        const __half* pwl_l = pwl + (size_t)l * C_ * C_;
        const __half* w1h_l = w1h + (size_t)l * C_ * F_;
        const __half* w2h_l = w2h + (size_t)l * F_ * C_;
        const __half* w2l_l = w2l + (size_t)l * F_ * C_;

        layernorm_kernel<<<M_ / 8, 256>>>(px, ln1_s + (size_t)l * C_, ln1_b + (size_t)l * C_, ln16);

        // qkv = ln @ qkv_w + qkv_b  -> fp16, 1-term (softmax-shielded)
        tc_gemm<1,0,0,1,1,128><<<dim3(M_ / 128, 3 * C_ / 128), 256, SM_1T128>>>(
            ln16, qwh_l, nullptr, qkv_b + (size_t)l * 3 * C_, nullptr,
            nullptr, qkv16, M_, 3 * C_, 3 * C_, C_);

        attn_kernel<<<dim3(T_ / 64, B_ * H_), 128>>>(qkv16, att16);

        // x = x + att @ proj_w + proj_b   (2-term, BM=64 for wave balance)
        tc_gemm<1,0,1,0,2,64><<<dim3(M_ / 64, C_ / 128), 256, SM_2T64>>>(
            att16, pwh_l, pwl_l, proj_b + (size_t)l * C_, px,
            px, nullptr, M_, C_, C_, C_);

        layernorm_kernel<<<M_ / 8, 256>>>(px, ln2_s + (size_t)l * C_, ln2_b + (size_t)l * C_, ln16);

        // mid = gelu(ln2 @ w1 + b1) -> fp16, 1-term (GELU-shielded)
        tc_gemm<1,1,0,1,1,128><<<dim3(M_ / 128, F_ / 128), 256, SM_1T128>>>(
            ln16, w1h_l, nullptr, b1 + (size_t)l * F_, nullptr,
            nullptr, mid16, M_, F_, F_, C_);

        // x = x + mid @ w2 + b2   (2-term, BM=64 for wave balance)
        tc_gemm<1,0,1,0,2,64><<<dim3(M_ / 64, C_ / 128), 256, SM_2T64>>>(
            mid16, w2h_l, w2l_l, b2 + (size_t)l * C_, px,
            px, nullptr, M_, C_, C_, F_);
    }

    layernorm_kernel<<<M_ / 8, 256>>>(px, lnf_s, lnf_b, ln16);

    // logits = lnf @ head_w, single fp16 term, N padded to 50304
    tc_gemm<0,0,0,0,1,128><<<dim3(M_ / 128, VP_ / 128), 256, SM_1T128>>>(
        ln16, hwh, nullptr, nullptr, nullptr,
        out, nullptr, M_, VP_, V_, C_);
}

// round 12
// speedup vs baseline: 1.0492x; 1.0492x over previous
#include <cuda_runtime.h>
#include <cuda_fp16.h>
#include <math.h>
#include <stdint.h>

// ---------------- problem constants ----------------
#define L_  6
#define B_  2
#define T_  1024
#define C_  768
#define H_  12
#define D_  64
#define F_  3072
#define V_  50257
#define VP_ 50304              // V padded to /128
#define M_  (B_ * T_)          // 2048 rows
#define EPS_ 1e-5f

// ---------------- scratch (device globals, no runtime alloc) ----------------
__device__ float  g_x    [M_ * C_];     // residual stream (fp32)
__device__ __half g_qkv16[M_ * 3 * C_]; // qkv (fp16)

// single-plane fp16 activations
__device__ __half g_ln16 [M_ * C_];
__device__ __half g_att16[M_ * C_];
__device__ __half g_mid16[M_ * F_];

// weight planes, converted once per replay
__device__ __half g_qkvw_h[L_ * C_ * 3 * C_];                       // 1-term
__device__ __half g_projw_h[L_ * C_ * C_], g_projw_l[L_ * C_ * C_]; // 2-term
__device__ __half g_w1_h  [L_ * C_ * F_];                           // 1-term
__device__ __half g_w2_h  [L_ * F_ * C_], g_w2_l  [L_ * F_ * C_];   // 2-term
__device__ __half g_hw_h  [C_ * VP_];                               // 1-term

// ---------------- helpers ----------------
__device__ __forceinline__ uint32_t smem_u32(const void* p) {
    uint32_t a;
    asm("{ .reg .u64 t; cvta.to.shared.u64 t, %1; cvt.u32.u64 %0, t; }" : "=r"(a) : "l"(p));
    return a;
}
__device__ __forceinline__ void cp16(uint32_t dst, const void* src) {
    asm volatile("cp.async.cg.shared.global [%0], [%1], 16;" :: "r"(dst), "l"(src));
}
__device__ __forceinline__ void cp_commit() {
    asm volatile("cp.async.commit_group;" ::: "memory");
}
__device__ __forceinline__ void ldsm_x4(uint32_t* r, uint32_t a) {
    asm volatile("ldmatrix.sync.aligned.m8n8.x4.shared.b16 {%0,%1,%2,%3}, [%4];"
        : "=r"(r[0]), "=r"(r[1]), "=r"(r[2]), "=r"(r[3]) : "r"(a));
}
__device__ __forceinline__ void ldsm_x2(uint32_t* r, uint32_t a) {
    asm volatile("ldmatrix.sync.aligned.m8n8.x2.shared.b16 {%0,%1}, [%2];"
        : "=r"(r[0]), "=r"(r[1]) : "r"(a));
}
__device__ __forceinline__ void ldsm_x2t(uint32_t* r, uint32_t a) {
    asm volatile("ldmatrix.sync.aligned.m8n8.x2.trans.shared.b16 {%0,%1}, [%2];"
        : "=r"(r[0]), "=r"(r[1]) : "r"(a));
}
__device__ __forceinline__ void mma_f16(float* d, const uint32_t* a, const uint32_t* b) {
    asm volatile("mma.sync.aligned.m16n8k16.row.col.f32.f16.f16.f32 "
        "{%0,%1,%2,%3}, {%4,%5,%6,%7}, {%8,%9}, {%0,%1,%2,%3};"
        : "+f"(d[0]), "+f"(d[1]), "+f"(d[2]), "+f"(d[3])
        : "r"(a[0]), "r"(a[1]), "r"(a[2]), "r"(a[3]), "r"(b[0]), "r"(b[1]));
}
__device__ __forceinline__ uint32_t packh2(float a, float b) {
    __half2 t = __floats2half2_rn(a, b);
    return *(uint32_t*)&t;
}
__device__ __forceinline__ void split1h(float x, __half& h, __half& l) {
    h = __float2half_rn(x);
    l = __float2half_rn(x - __half2float(h));
}
__device__ __forceinline__ float gelu_exact(float v) {
    return 0.5f * v * (1.0f + erff(v * 0.70710678118654752f));
}

// ---------------- weight conversion (R10 form: one float4/thread) ----------------
__global__ void convert_kernel(const float* __restrict__ src,
                               __half* __restrict__ hi,
                               __half* __restrict__ lo, int n4) {
    int e = blockIdx.x * blockDim.x + threadIdx.x;
    if (e >= n4) return;
    float4 v = *(const float4*)(src + (size_t)e * 4);
    __half h[4], l[4];
    split1h(v.x, h[0], l[0]); split1h(v.y, h[1], l[1]);
    split1h(v.z, h[2], l[2]); split1h(v.w, h[3], l[3]);
    *(__half2*)(hi + (size_t)e * 4)     = *(__half2*)&h[0];
    *(__half2*)(hi + (size_t)e * 4 + 2) = *(__half2*)&h[2];
    *(__half2*)(lo + (size_t)e * 4)     = *(__half2*)&l[0];
    *(__half2*)(lo + (size_t)e * 4 + 2) = *(__half2*)&l[2];
}

__global__ void convert_hi_kernel(const float* __restrict__ src,
                                  __half* __restrict__ hi, int n4) {
    int e = blockIdx.x * blockDim.x + threadIdx.x;
    if (e >= n4) return;
    float4 v = *(const float4*)(src + (size_t)e * 4);
    __half h[4];
    h[0] = __float2half_rn(v.x); h[1] = __float2half_rn(v.y);
    h[2] = __float2half_rn(v.z); h[3] = __float2half_rn(v.w);
    *(__half2*)(hi + (size_t)e * 4)     = *(__half2*)&h[0];
    *(__half2*)(hi + (size_t)e * 4 + 2) = *(__half2*)&h[2];
}

// head_w [C_ x V_] -> padded single fp16 plane [C_ x VP_]
__global__ void convert_head_kernel(const float* __restrict__ src,
                                    __half* __restrict__ hi) {
    int e = blockIdx.x * blockDim.x + threadIdx.x;
    if (e >= C_ * (VP_ / 4)) return;
    int row = e / (VP_ / 4);
    int c0  = (e % (VP_ / 4)) * 4;
    __half h[4];
    #pragma unroll
    for (int j = 0; j < 4; j++) {
        int c = c0 + j;
        h[j] = __float2half_rn((c < V_) ? src[(size_t)row * V_ + c] : 0.0f);
    }
    size_t o = (size_t)row * VP_ + c0;
    *(__half2*)(hi + o)     = *(__half2*)&h[0];
    *(__half2*)(hi + o + 2) = *(__half2*)&h[2];
}

// ---------------- embedding ----------------
__global__ void embed_kernel(const int* __restrict__ idx,
                             const float* __restrict__ wte,
                             const float* __restrict__ pte,
                             float* __restrict__ x) {
    int r = blockIdx.x;
    int t = r % T_;
    int tok = idx[r];
    const float* wrow = wte + (size_t)tok * C_;
    const float* prow = pte + (size_t)t * C_;
    float* xr = x + (size_t)r * C_;
    for (int c = threadIdx.x; c < C_; c += blockDim.x)
        xr[c] = wrow[c] + prow[c];
}

// ---------------- layernorm: warp per row, shuffle reduce -> fp16 ----------------
// grid M_/8, block 256 (8 warps)
__global__ __launch_bounds__(256) void layernorm_kernel(
        const float* __restrict__ x,
        const float* __restrict__ sc,
        const float* __restrict__ bi,
        __half* __restrict__ y) {
    int w = threadIdx.x >> 5, lane = threadIdx.x & 31;
    int r = blockIdx.x * 8 + w;
    const float* xr = x + (size_t)r * C_;
    float v[24];
    float s = 0.0f, ss = 0.0f;
    #pragma unroll
    for (int i = 0; i < 6; i++) {
        float4 t = *(const float4*)(xr + (i * 32 + lane) * 4);
        v[i*4+0] = t.x; v[i*4+1] = t.y; v[i*4+2] = t.z; v[i*4+3] = t.w;
        s  += t.x + t.y + t.z + t.w;
        ss += t.x*t.x + t.y*t.y + t.z*t.z + t.w*t.w;
    }
    #pragma unroll
    for (int off = 16; off > 0; off >>= 1) {
        s  += __shfl_xor_sync(0xffffffff, s, off);
        ss += __shfl_xor_sync(0xffffffff, ss, off);
    }
    float mu   = s * (1.0f / C_);
    float var  = ss * (1.0f / C_) - mu * mu;
    float rstd = rsqrtf(var + EPS_);
    size_t base = (size_t)r * C_;
    #pragma unroll
    for (int i = 0; i < 6; i++) {
        int col = (i * 32 + lane) * 4;
        float4 scv = *(const float4*)(sc + col);
        float4 biv = *(const float4*)(bi + col);
        __half h[4];
        h[0] = __float2half_rn((v[i*4+0] - mu) * rstd * scv.x + biv.x);
        h[1] = __float2half_rn((v[i*4+1] - mu) * rstd * scv.y + biv.y);
        h[2] = __float2half_rn((v[i*4+2] - mu) * rstd * scv.z + biv.z);
        h[3] = __float2half_rn((v[i*4+3] - mu) * rstd * scv.w + biv.w);
        *(uint2*)(y + base + col) = *(uint2*)&h[0];
    }
}

// ---------------- FA2-style block attention, fp16 qkv, cp.async tiles ----------------
__global__ __launch_bounds__(128) void attn_kernel(const __half* __restrict__ qkv,
                                                   __half* __restrict__ o16) {
    __shared__ __align__(1024) __half sQ[64 * 64];
    __shared__ __align__(1024) __half sK[64 * 64];
    __shared__ __align__(1024) __half sV[64 * 64];
    uint32_t qB = smem_u32(sQ), kB = smem_u32(sK), vB = smem_u32(sV);
    int tid = threadIdx.x, lane = tid & 31, wid = tid >> 5;
    int q0 = blockIdx.x * 64;
    int bh = blockIdx.y;
    int b = bh / H_, h = bh % H_;
    const __half* base = qkv + (size_t)b * T_ * 3 * C_ + h * D_;

    #pragma unroll
    for (int i = 0; i < 4; i++) {
        int e = tid + 128 * i;
        int r = e >> 3, u = e & 7;
        uint32_t d = qB + (uint32_t)(r * 128 + ((u ^ (r & 7)) << 4));
        cp16(d, base + (size_t)(q0 + r) * 3 * C_ + u * 8);
    }
    cp_commit();
    asm volatile("cp.async.wait_group 0;" ::: "memory");
    __syncthreads();

    uint32_t qa[4][4];
    #pragma unroll
    for (int ks = 0; ks < 4; ks++) {
        int r = wid * 16 + (lane & 15);
        int c = ks * 2 + (lane >> 4);
        ldsm_x4(qa[ks], qB + (uint32_t)(r * 128 + ((c ^ (r & 7)) << 4)));
    }

    float m1 = -1e30f, m2 = -1e30f, l1 = 0.0f, l2 = 0.0f;
    float oacc[8][4];
    #pragma unroll
    for (int dt = 0; dt < 8; dt++)
        #pragma unroll
        for (int i = 0; i < 4; i++) oacc[dt][i] = 0.0f;

    int r1loc = wid * 16 + (lane >> 2);

    for (int j0 = 0; j0 <= q0; j0 += 64) {
        __syncthreads();
        #pragma unroll
        for (int i = 0; i < 4; i++) {
            int e = tid + 128 * i;
            int r = e >> 3, u = e & 7;
            uint32_t off = (uint32_t)(r * 128 + ((u ^ (r & 7)) << 4));
            cp16(kB + off, base + C_     + (size_t)(j0 + r) * 3 * C_ + u * 8);
            cp16(vB + off, base + 2 * C_ + (size_t)(j0 + r) * 3 * C_ + u * 8);
        }
        cp_commit();
        asm volatile("cp.async.wait_group 0;" ::: "memory");
        __syncthreads();

        float sc[8][4];
        #pragma unroll
        for (int nt = 0; nt < 8; nt++)
            #pragma unroll
            for (int i = 0; i < 4; i++) sc[nt][i] = 0.0f;
        #pragma unroll
        for (int ks = 0; ks < 4; ks++) {
            #pragma unroll
            for (int nt = 0; nt < 8; nt++) {
                int n = nt * 8 + (lane & 7);
                int g = ks * 2 + ((lane >> 3) & 1);
                uint32_t kb[2];
                ldsm_x2(kb, kB + (uint32_t)(n * 128 + ((g ^ (n & 7)) << 4)));
                mma_f16(sc[nt], qa[ks], kb);
            }
        }
        #pragma unroll
        for (int nt = 0; nt < 8; nt++)
            #pragma unroll
            for (int i = 0; i < 4; i++) sc[nt][i] *= 0.125f;

        if (j0 == q0) {
            #pragma unroll
            for (int nt = 0; nt < 8; nt++) {
                int cb = nt * 8 + (lane & 3) * 2;
                if (cb     > r1loc) sc[nt][0] = -1e30f;
                if (cb + 1 > r1loc) sc[nt][1] = -1e30f;
                if (cb     > r1loc + 8) sc[nt][2] = -1e30f;
                if (cb + 1 > r1loc + 8) sc[nt][3] = -1e30f;
            }
        }

        float nm1 = m1, nm2 = m2;
        #pragma unroll
        for (int nt = 0; nt < 8; nt++) {
            nm1 = fmaxf(nm1, fmaxf(sc[nt][0], sc[nt][1]));
            nm2 = fmaxf(nm2, fmaxf(sc[nt][2], sc[nt][3]));
        }
        #pragma unroll
        for (int o = 1; o <= 2; o <<= 1) {
            nm1 = fmaxf(nm1, __shfl_xor_sync(0xffffffff, nm1, o));
            nm2 = fmaxf(nm2, __shfl_xor_sync(0xffffffff, nm2, o));
        }
        float corr1 = __expf(m1 - nm1);
        float corr2 = __expf(m2 - nm2);
        m1 = nm1; m2 = nm2;
        float rs1 = 0.0f, rs2 = 0.0f;
        #pragma unroll
        for (int nt = 0; nt < 8; nt++) {
            sc[nt][0] = __expf(sc[nt][0] - m1);
            sc[nt][1] = __expf(sc[nt][1] - m1);
            sc[nt][2] = __expf(sc[nt][2] - m2);
            sc[nt][3] = __expf(sc[nt][3] - m2);
            rs1 += sc[nt][0] + sc[nt][1];
            rs2 += sc[nt][2] + sc[nt][3];
        }
        #pragma unroll
        for (int o = 1; o <= 2; o <<= 1) {
            rs1 += __shfl_xor_sync(0xffffffff, rs1, o);
            rs2 += __shfl_xor_sync(0xffffffff, rs2, o);
        }
        l1 = l1 * corr1 + rs1;
        l2 = l2 * corr2 + rs2;
        #pragma unroll
        for (int dt = 0; dt < 8; dt++) {
            oacc[dt][0] *= corr1; oacc[dt][1] *= corr1;
            oacc[dt][2] *= corr2; oacc[dt][3] *= corr2;
        }

        #pragma unroll
        for (int ks = 0; ks < 4; ks++) {
            uint32_t pa[4];
            pa[0] = packh2(sc[2 * ks][0],     sc[2 * ks][1]);
            pa[1] = packh2(sc[2 * ks][2],     sc[2 * ks][3]);
            pa[2] = packh2(sc[2 * ks + 1][0], sc[2 * ks + 1][1]);
            pa[3] = packh2(sc[2 * ks + 1][2], sc[2 * ks + 1][3]);
            #pragma unroll
            for (int dt = 0; dt < 8; dt++) {
                int kt = ks * 16 + (lane & 15);
                uint32_t vb[2];
                ldsm_x2t(vb, vB + (uint32_t)(kt * 128 + ((dt ^ (kt & 7)) << 4)));
                mma_f16(oacc[dt], pa, vb);
            }
        }
    }

    float inv1 = 1.0f / l1, inv2 = 1.0f / l2;
    int rowg = b * T_ + q0 + r1loc;
    #pragma unroll
    for (int dt = 0; dt < 8; dt++) {
        int col = h * D_ + dt * 8 + (lane & 3) * 2;
        *(__half2*)(o16 + (size_t)rowg * C_ + col) =
            __floats2half2_rn(oacc[dt][0] * inv1, oacc[dt][1] * inv1);
        *(__half2*)(o16 + (size_t)(rowg + 8) * C_ + col) =
            __floats2half2_rn(oacc[dt][2] * inv2, oacc[dt][3] * inv2);
    }
}

// ================= fp16 GEMM: C = A*(Bh[+Bl]), 3-stage cp.async =================
// Tile 128x128, BK=64, 256 threads.
template<int HAS_BIAS, int DO_GELU, int DO_RES, int WRITE_F16, int TERMS>
__global__ __launch_bounds__(256, 1) void tc_gemm(
        const __half* __restrict__ Af,
        const __half* __restrict__ Bhi, const __half* __restrict__ Blo,
        const float* __restrict__ bias, const float* __restrict__ res,
        float* __restrict__ Cf, __half* __restrict__ C16,
        int M, int Nb, int Nc, int K) {
    constexpr uint32_t STGB = (TERMS == 2) ? 49152u : 32768u;
    extern __shared__ __align__(1024) char dsm[];
    uint32_t sb = smem_u32(dsm);
    const int tid = threadIdx.x, lane = tid & 31, wid = tid >> 5;
    const int wm = wid >> 2, wn = wid & 3;
    const int m0 = blockIdx.x * 128, n0 = blockIdx.y * 128;
    const int niter = K >> 6;

    float acc[4][4][4];
    #pragma unroll
    for (int a = 0; a < 4; a++)
        #pragma unroll
        for (int b = 0; b < 4; b++)
            #pragma unroll
            for (int c = 0; c < 4; c++) acc[a][b][c] = 0.0f;

    auto PREFETCH = [&](int it) {
        if (it < niter) {
            int k0 = it << 6;
            uint32_t buf = sb + (it % 3) * STGB;
            #pragma unroll
            for (int i = 0; i < 4; i++) {
                int e = tid + 256 * i;
                int r = e >> 3, u = e & 7;
                uint32_t d = buf + (uint32_t)(r * 128 + ((u ^ (r & 7)) << 4));
                cp16(d, Af + (size_t)(m0 + r) * K + k0 + u * 8);
            }
            #pragma unroll
            for (int i = 0; i < 4; i++) {
                int e = tid + 256 * i;
                int kr = e >> 4, u = e & 15;
                uint32_t d = buf + 16384 + (uint32_t)(kr * 256 + ((u ^ (kr & 7)) << 4));
                size_t so = (size_t)(k0 + kr) * Nb + n0 + u * 8;
                cp16(d, Bhi + so);
                if (TERMS == 2) cp16(d + 16384, Blo + so);
            }
        }
        cp_commit();
    };

    auto COMPUTE = [&](int stg) {
        uint32_t aBase = sb + stg * STGB;
        uint32_t bBase = aBase + 16384;
        #pragma unroll
        for (int ks = 0; ks < 4; ks++) {
            uint32_t af[4][4];
            #pragma unroll
            for (int mt = 0; mt < 4; mt++) {
                int r = wm * 64 + mt * 16 + (lane & 15);
                int c = ks * 2 + (lane >> 4);
                uint32_t off = (uint32_t)(r * 128 + ((c ^ (r & 7)) << 4));
                ldsm_x4(af[mt], aBase + off);
            }
            uint32_t bh[4][2], blr[4][2];
            #pragma unroll
            for (int nt = 0; nt < 4; nt++) {
                int kt = ks * 16 + (lane & 15);
                int c = wn * 4 + nt;
                uint32_t off = (uint32_t)(kt * 256 + ((c ^ (kt & 7)) << 4));
                ldsm_x2t(bh[nt],  bBase + off);
                if (TERMS == 2) ldsm_x2t(blr[nt], bBase + 16384 + off);
            }
            #pragma unroll
            for (int mt = 0; mt < 4; mt++)
                #pragma unroll
                for (int nt = 0; nt < 4; nt++) {
                    mma_f16(acc[mt][nt], af[mt], bh[nt]);
                    if (TERMS == 2) mma_f16(acc[mt][nt], af[mt], blr[nt]);
                }
        }
    };

    PREFETCH(0);
    PREFETCH(1);
    for (int it = 0; it < niter; it++) {
        asm volatile("cp.async.wait_group 1;" ::: "memory");
        __syncthreads();
        COMPUTE(it % 3);
        PREFETCH(it + 2);
    }

    #pragma unroll
    for (int mt = 0; mt < 4; mt++) {
        int r0 = m0 + wm * 64 + mt * 16 + (lane >> 2);
        #pragma unroll
        for (int nt = 0; nt < 4; nt++) {
            int c0 = n0 + wn * 32 + nt * 8 + (lane & 3) * 2;
            float v[4];
            #pragma unroll
            for (int i = 0; i < 4; i++) {
                v[i] = acc[mt][nt][i];
                int col = c0 + (i & 1);
                if (HAS_BIAS && col < Nc) v[i] += bias[col];
                if (DO_GELU) v[i] = gelu_exact(v[i]);
            }
            if (WRITE_F16) {
                #pragma unroll
                for (int half_i = 0; half_i < 2; half_i++) {
                    int row = r0 + half_i * 8;
                    size_t o = (size_t)row * Nc + c0;
                    *(__half2*)(C16 + o) =
                        __floats2half2_rn(v[half_i * 2], v[half_i * 2 + 1]);
                }
            } else {
                #pragma unroll
                for (int i = 0; i < 4; i++) {
                    int row = r0 + (i >> 1) * 8;
                    int col = c0 + (i & 1);
                    if (col < Nc) {
                        float w = v[i];
                        if (DO_RES) w += res[(size_t)row * Nc + col];
                        Cf[(size_t)row * Nc + col] = w;
                    }
                }
            }
        }
    }
}

// ---------------- launch ----------------
extern "C" void kernel_launch(void* const* d_in, const int* in_sizes, int n_in,
                              void* d_out, int out_size) {
    const int*   idx    = (const int*)  d_in[0];
    const float* wte    = (const float*)d_in[1];
    const float* pte    = (const float*)d_in[2];
    const float* ln1_s  = (const float*)d_in[3];
    const float* ln1_b  = (const float*)d_in[4];
    const float* qkv_w  = (const float*)d_in[5];
    const float* qkv_b  = (const float*)d_in[6];
    const float* proj_w = (const float*)d_in[7];
    const float* proj_b = (const float*)d_in[8];
    const float* ln2_s  = (const float*)d_in[9];
    const float* ln2_b  = (const float*)d_in[10];
    const float* w1     = (const float*)d_in[11];
    const float* b1     = (const float*)d_in[12];
    const float* w2     = (const float*)d_in[13];
    const float* b2     = (const float*)d_in[14];
    const float* lnf_s  = (const float*)d_in[15];
    const float* lnf_b  = (const float*)d_in[16];
    const float* head_w = (const float*)d_in[17];
    float* out = (float*)d_out;

    float* px;
    cudaGetSymbolAddress((void**)&px, g_x);
    __half *qkv16, *ln16, *att16, *mid16;
    cudaGetSymbolAddress((void**)&qkv16, g_qkv16);
    cudaGetSymbolAddress((void**)&ln16,  g_ln16);
    cudaGetSymbolAddress((void**)&att16, g_att16);
    cudaGetSymbolAddress((void**)&mid16, g_mid16);
    __half *qwh, *pwh, *pwl, *w1h, *w2h, *w2l, *hwh;
    cudaGetSymbolAddress((void**)&qwh, g_qkvw_h);
    cudaGetSymbolAddress((void**)&pwh, g_projw_h); cudaGetSymbolAddress((void**)&pwl, g_projw_l);
    cudaGetSymbolAddress((void**)&w1h, g_w1_h);
    cudaGetSymbolAddress((void**)&w2h, g_w2_h);   cudaGetSymbolAddress((void**)&w2l, g_w2_l);
    cudaGetSymbolAddress((void**)&hwh, g_hw_h);

    cudaFuncSetAttribute(tc_gemm<1,0,0,1,1>, cudaFuncAttributeMaxDynamicSharedMemorySize, 3 * 32768);
    cudaFuncSetAttribute(tc_gemm<1,0,1,0,2>, cudaFuncAttributeMaxDynamicSharedMemorySize, 3 * 49152);
    cudaFuncSetAttribute(tc_gemm<1,1,0,1,1>, cudaFuncAttributeMaxDynamicSharedMemorySize, 3 * 32768);
    cudaFuncSetAttribute(tc_gemm<0,0,0,0,1>, cudaFuncAttributeMaxDynamicSharedMemorySize, 3 * 32768);

    // ---- weight conversion (once per replay) ----
    {
        int n;
        n = L_ * C_ * 3 * C_ / 4;
        convert_hi_kernel<<<(n + 255) / 256, 256>>>(qkv_w, qwh, n);
        n = L_ * C_ * C_ / 4;
        convert_kernel<<<(n + 255) / 256, 256>>>(proj_w, pwh, pwl, n);
        n = L_ * C_ * F_ / 4;
        convert_hi_kernel<<<(n + 255) / 256, 256>>>(w1, w1h, n);
        n = L_ * F_ * C_ / 4;
        convert_kernel<<<(n + 255) / 256, 256>>>(w2, w2h, w2l, n);
        n = C_ * VP_ / 4;
        convert_head_kernel<<<(n + 255) / 256, 256>>>(head_w, hwh);
    }

    embed_kernel<<<M_, 256>>>(idx, wte, pte, px);

    for (int l = 0; l < L_; l++) {
        const __half* qwh_l = qwh + (size_t)l * C_ * 3 * C_;
        const __half* pwh_l = pwh + (size_t)l * C_ * C_;
        const __half* pwl_l = pwl + (size_t)l * C_ * C_;
        const __half* w1h_l = w1h + (size_t)l * C_ * F_;
        const __half* w2h_l = w2h + (size_t)l * F_ * C_;
        const __half* w2l_l = w2l + (size_t)l * F_ * C_;

        layernorm_kernel<<<M_ / 8, 256>>>(px, ln1_s + (size_t)l * C_, ln1_b + (size_t)l * C_, ln16);

        // qkv = ln @ qkv_w + qkv_b  -> fp16, 1-term (softmax-shielded)
        tc_gemm<1,0,0,1,1><<<dim3(M_ / 128, 3 * C_ / 128), 256, 3 * 32768>>>(
            ln16, qwh_l, nullptr, qkv_b + (size_t)l * 3 * C_, nullptr,
            nullptr, qkv16, M_, 3 * C_, 3 * C_, C_);

        attn_kernel<<<dim3(T_ / 64, B_ * H_), 128>>>(qkv16, att16);

        // x = x + att @ proj_w + proj_b   (2-term: residual writer)
        tc_gemm<1,0,1,0,2><<<dim3(M_ / 128, C_ / 128), 256, 3 * 49152>>>(
            att16, pwh_l, pwl_l, proj_b + (size_t)l * C_, px,
            px, nullptr, M_, C_, C_, C_);

        layernorm_kernel<<<M_ / 8, 256>>>(px, ln2_s + (size_t)l * C_, ln2_b + (size_t)l * C_, ln16);

        // mid = gelu(ln2 @ w1 + b1) -> fp16, 1-term (GELU-shielded)
        tc_gemm<1,1,0,1,1><<<dim3(M_ / 128, F_ / 128), 256, 3 * 32768>>>(
            ln16, w1h_l, nullptr, b1 + (size_t)l * F_, nullptr,
            nullptr, mid16, M_, F_, F_, C_);

        // x = x + mid @ w2 + b2   (2-term: residual writer)
        tc_gemm<1,0,1,0,2><<<dim3(M_ / 128, C_ / 128), 256, 3 * 49152>>>(
            mid16, w2h_l, w2l_l, b2 + (size_t)l * C_, px,
            px, nullptr, M_, C_, C_, F_);
    }

    layernorm_kernel<<<M_ / 8, 256>>>(px, lnf_s, lnf_b, ln16);

    // logits = lnf @ head_w, single fp16 term, N padded to 50304
    tc_gemm<0,0,0,0,1><<<dim3(M_ / 128, VP_ / 128), 256, 3 * 32768>>>(
        ln16, hwh, nullptr, nullptr, nullptr,
        out, nullptr, M_, VP_, V_, C_);
}

// round 13
// speedup vs baseline: 1.0935x; 1.0422x over previous
#include <cuda_runtime.h>
#include <cuda_fp16.h>
#include <math.h>
#include <stdint.h>

// ---------------- problem constants ----------------
#define L_  6
#define B_  2
#define T_  1024
#define C_  768
#define H_  12
#define D_  64
#define F_  3072
#define V_  50257
#define VP_ 50304              // V padded to /128
#define M_  (B_ * T_)          // 2048 rows
#define EPS_ 1e-5f

// ---------------- scratch (device globals, no runtime alloc) ----------------
__device__ float  g_x    [M_ * C_];     // residual stream (fp32)
__device__ __half g_qkv16[M_ * 3 * C_]; // qkv (fp16)

// single-plane fp16 activations
__device__ __half g_ln16 [M_ * C_];
__device__ __half g_att16[M_ * C_];
__device__ __half g_mid16[M_ * F_];

// weight planes, converted once per replay
__device__ __half g_qkvw_h[L_ * C_ * 3 * C_];                       // 1-term
__device__ __half g_projw_h[L_ * C_ * C_], g_projw_l[L_ * C_ * C_]; // 2-term
__device__ __half g_w1_h  [L_ * C_ * F_];                           // 1-term
__device__ __half g_w2_h  [L_ * F_ * C_], g_w2_l  [L_ * F_ * C_];   // 2-term
__device__ __half g_hw_h  [C_ * VP_];                               // 1-term

// ---------------- helpers ----------------
__device__ __forceinline__ uint32_t smem_u32(const void* p) {
    uint32_t a;
    asm("{ .reg .u64 t; cvta.to.shared.u64 t, %1; cvt.u32.u64 %0, t; }" : "=r"(a) : "l"(p));
    return a;
}
__device__ __forceinline__ void cp16(uint32_t dst, const void* src) {
    asm volatile("cp.async.cg.shared.global [%0], [%1], 16;" :: "r"(dst), "l"(src));
}
__device__ __forceinline__ void cp_commit() {
    asm volatile("cp.async.commit_group;" ::: "memory");
}
__device__ __forceinline__ void ldsm_x4(uint32_t* r, uint32_t a) {
    asm volatile("ldmatrix.sync.aligned.m8n8.x4.shared.b16 {%0,%1,%2,%3}, [%4];"
        : "=r"(r[0]), "=r"(r[1]), "=r"(r[2]), "=r"(r[3]) : "r"(a));
}
__device__ __forceinline__ void ldsm_x2(uint32_t* r, uint32_t a) {
    asm volatile("ldmatrix.sync.aligned.m8n8.x2.shared.b16 {%0,%1}, [%2];"
        : "=r"(r[0]), "=r"(r[1]) : "r"(a));
}
__device__ __forceinline__ void ldsm_x2t(uint32_t* r, uint32_t a) {
    asm volatile("ldmatrix.sync.aligned.m8n8.x2.trans.shared.b16 {%0,%1}, [%2];"
        : "=r"(r[0]), "=r"(r[1]) : "r"(a));
}
__device__ __forceinline__ void mma_f16(float* d, const uint32_t* a, const uint32_t* b) {
    asm volatile("mma.sync.aligned.m16n8k16.row.col.f32.f16.f16.f32 "
        "{%0,%1,%2,%3}, {%4,%5,%6,%7}, {%8,%9}, {%0,%1,%2,%3};"
        : "+f"(d[0]), "+f"(d[1]), "+f"(d[2]), "+f"(d[3])
        : "r"(a[0]), "r"(a[1]), "r"(a[2]), "r"(a[3]), "r"(b[0]), "r"(b[1]));
}
__device__ __forceinline__ uint32_t packh2(float a, float b) {
    __half2 t = __floats2half2_rn(a, b);
    return *(uint32_t*)&t;
}
__device__ __forceinline__ void split1h(float x, __half& h, __half& l) {
    h = __float2half_rn(x);
    l = __float2half_rn(x - __half2float(h));
}
__device__ __forceinline__ float gelu_exact(float v) {
    return 0.5f * v * (1.0f + erff(v * 0.70710678118654752f));
}

// ---------------- weight conversion (one float4/thread) ----------------
__global__ void convert_kernel(const float* __restrict__ src,
                               __half* __restrict__ hi,
                               __half* __restrict__ lo, int n4) {
    int e = blockIdx.x * blockDim.x + threadIdx.x;
    if (e >= n4) return;
    float4 v = *(const float4*)(src + (size_t)e * 4);
    __half h[4], l[4];
    split1h(v.x, h[0], l[0]); split1h(v.y, h[1], l[1]);
    split1h(v.z, h[2], l[2]); split1h(v.w, h[3], l[3]);
    *(__half2*)(hi + (size_t)e * 4)     = *(__half2*)&h[0];
    *(__half2*)(hi + (size_t)e * 4 + 2) = *(__half2*)&h[2];
    *(__half2*)(lo + (size_t)e * 4)     = *(__half2*)&l[0];
    *(__half2*)(lo + (size_t)e * 4 + 2) = *(__half2*)&l[2];
}

__global__ void convert_hi_kernel(const float* __restrict__ src,
                                  __half* __restrict__ hi, int n4) {
    int e = blockIdx.x * blockDim.x + threadIdx.x;
    if (e >= n4) return;
    float4 v = *(const float4*)(src + (size_t)e * 4);
    __half h[4];
    h[0] = __float2half_rn(v.x); h[1] = __float2half_rn(v.y);
    h[2] = __float2half_rn(v.z); h[3] = __float2half_rn(v.w);
    *(__half2*)(hi + (size_t)e * 4)     = *(__half2*)&h[0];
    *(__half2*)(hi + (size_t)e * 4 + 2) = *(__half2*)&h[2];
}

// head_w [C_ x V_] -> padded single fp16 plane [C_ x VP_]
__global__ void convert_head_kernel(const float* __restrict__ src,
                                    __half* __restrict__ hi) {
    int e = blockIdx.x * blockDim.x + threadIdx.x;
    if (e >= C_ * (VP_ / 4)) return;
    int row = e / (VP_ / 4);
    int c0  = (e % (VP_ / 4)) * 4;
    __half h[4];
    #pragma unroll
    for (int j = 0; j < 4; j++) {
        int c = c0 + j;
        h[j] = __float2half_rn((c < V_) ? src[(size_t)row * V_ + c] : 0.0f);
    }
    size_t o = (size_t)row * VP_ + c0;
    *(__half2*)(hi + o)     = *(__half2*)&h[0];
    *(__half2*)(hi + o + 2) = *(__half2*)&h[2];
}

// ---------------- embedding ----------------
__global__ void embed_kernel(const int* __restrict__ idx,
                             const float* __restrict__ wte,
                             const float* __restrict__ pte,
                             float* __restrict__ x) {
    int r = blockIdx.x;
    int t = r % T_;
    int tok = idx[r];
    const float* wrow = wte + (size_t)tok * C_;
    const float* prow = pte + (size_t)t * C_;
    float* xr = x + (size_t)r * C_;
    for (int c = threadIdx.x; c < C_; c += blockDim.x)
        xr[c] = wrow[c] + prow[c];
}

// ---------------- layernorm: warp per row, shuffle reduce -> fp16 ----------------
__global__ __launch_bounds__(256) void layernorm_kernel(
        const float* __restrict__ x,
        const float* __restrict__ sc,
        const float* __restrict__ bi,
        __half* __restrict__ y) {
    int w = threadIdx.x >> 5, lane = threadIdx.x & 31;
    int r = blockIdx.x * 8 + w;
    const float* xr = x + (size_t)r * C_;
    float v[24];
    float s = 0.0f, ss = 0.0f;
    #pragma unroll
    for (int i = 0; i < 6; i++) {
        float4 t = *(const float4*)(xr + (i * 32 + lane) * 4);
        v[i*4+0] = t.x; v[i*4+1] = t.y; v[i*4+2] = t.z; v[i*4+3] = t.w;
        s  += t.x + t.y + t.z + t.w;
        ss += t.x*t.x + t.y*t.y + t.z*t.z + t.w*t.w;
    }
    #pragma unroll
    for (int off = 16; off > 0; off >>= 1) {
        s  += __shfl_xor_sync(0xffffffff, s, off);
        ss += __shfl_xor_sync(0xffffffff, ss, off);
    }
    float mu   = s * (1.0f / C_);
    float var  = ss * (1.0f / C_) - mu * mu;
    float rstd = rsqrtf(var + EPS_);
    size_t base = (size_t)r * C_;
    #pragma unroll
    for (int i = 0; i < 6; i++) {
        int col = (i * 32 + lane) * 4;
        float4 scv = *(const float4*)(sc + col);
        float4 biv = *(const float4*)(bi + col);
        __half h[4];
        h[0] = __float2half_rn((v[i*4+0] - mu) * rstd * scv.x + biv.x);
        h[1] = __float2half_rn((v[i*4+1] - mu) * rstd * scv.y + biv.y);
        h[2] = __float2half_rn((v[i*4+2] - mu) * rstd * scv.z + biv.z);
        h[3] = __float2half_rn((v[i*4+3] - mu) * rstd * scv.w + biv.w);
        *(uint2*)(y + base + col) = *(uint2*)&h[0];
    }
}

// ---------------- FA2-style block attention, fp16 qkv, cp.async tiles ----------------
// Longest (latest-q) tiles scheduled FIRST for makespan.
__global__ __launch_bounds__(128) void attn_kernel(const __half* __restrict__ qkv,
                                                   __half* __restrict__ o16) {
    __shared__ __align__(1024) __half sQ[64 * 64];
    __shared__ __align__(1024) __half sK[64 * 64];
    __shared__ __align__(1024) __half sV[64 * 64];
    uint32_t qB = smem_u32(sQ), kB = smem_u32(sK), vB = smem_u32(sV);
    int tid = threadIdx.x, lane = tid & 31, wid = tid >> 5;
    int q0 = (gridDim.x - 1 - blockIdx.x) * 64;   // heavy tiles first
    int bh = blockIdx.y;
    int b = bh / H_, h = bh % H_;
    const __half* base = qkv + (size_t)b * T_ * 3 * C_ + h * D_;

    #pragma unroll
    for (int i = 0; i < 4; i++) {
        int e = tid + 128 * i;
        int r = e >> 3, u = e & 7;
        uint32_t d = qB + (uint32_t)(r * 128 + ((u ^ (r & 7)) << 4));
        cp16(d, base + (size_t)(q0 + r) * 3 * C_ + u * 8);
    }
    cp_commit();
    asm volatile("cp.async.wait_group 0;" ::: "memory");
    __syncthreads();

    uint32_t qa[4][4];
    #pragma unroll
    for (int ks = 0; ks < 4; ks++) {
        int r = wid * 16 + (lane & 15);
        int c = ks * 2 + (lane >> 4);
        ldsm_x4(qa[ks], qB + (uint32_t)(r * 128 + ((c ^ (r & 7)) << 4)));
    }

    float m1 = -1e30f, m2 = -1e30f, l1 = 0.0f, l2 = 0.0f;
    float oacc[8][4];
    #pragma unroll
    for (int dt = 0; dt < 8; dt++)
        #pragma unroll
        for (int i = 0; i < 4; i++) oacc[dt][i] = 0.0f;

    int r1loc = wid * 16 + (lane >> 2);

    for (int j0 = 0; j0 <= q0; j0 += 64) {
        __syncthreads();
        #pragma unroll
        for (int i = 0; i < 4; i++) {
            int e = tid + 128 * i;
            int r = e >> 3, u = e & 7;
            uint32_t off = (uint32_t)(r * 128 + ((u ^ (r & 7)) << 4));
            cp16(kB + off, base + C_     + (size_t)(j0 + r) * 3 * C_ + u * 8);
            cp16(vB + off, base + 2 * C_ + (size_t)(j0 + r) * 3 * C_ + u * 8);
        }
        cp_commit();
        asm volatile("cp.async.wait_group 0;" ::: "memory");
        __syncthreads();

        float sc[8][4];
        #pragma unroll
        for (int nt = 0; nt < 8; nt++)
            #pragma unroll
            for (int i = 0; i < 4; i++) sc[nt][i] = 0.0f;
        #pragma unroll
        for (int ks = 0; ks < 4; ks++) {
            #pragma unroll
            for (int nt = 0; nt < 8; nt++) {
                int n = nt * 8 + (lane & 7);
                int g = ks * 2 + ((lane >> 3) & 1);
                uint32_t kb[2];
                ldsm_x2(kb, kB + (uint32_t)(n * 128 + ((g ^ (n & 7)) << 4)));
                mma_f16(sc[nt], qa[ks], kb);
            }
        }
        #pragma unroll
        for (int nt = 0; nt < 8; nt++)
            #pragma unroll
            for (int i = 0; i < 4; i++) sc[nt][i] *= 0.125f;

        if (j0 == q0) {
            #pragma unroll
            for (int nt = 0; nt < 8; nt++) {
                int cb = nt * 8 + (lane & 3) * 2;
                if (cb     > r1loc) sc[nt][0] = -1e30f;
                if (cb + 1 > r1loc) sc[nt][1] = -1e30f;
                if (cb     > r1loc + 8) sc[nt][2] = -1e30f;
                if (cb + 1 > r1loc + 8) sc[nt][3] = -1e30f;
            }
        }

        float nm1 = m1, nm2 = m2;
        #pragma unroll
        for (int nt = 0; nt < 8; nt++) {
            nm1 = fmaxf(nm1, fmaxf(sc[nt][0], sc[nt][1]));
            nm2 = fmaxf(nm2, fmaxf(sc[nt][2], sc[nt][3]));
        }
        #pragma unroll
        for (int o = 1; o <= 2; o <<= 1) {
            nm1 = fmaxf(nm1, __shfl_xor_sync(0xffffffff, nm1, o));
            nm2 = fmaxf(nm2, __shfl_xor_sync(0xffffffff, nm2, o));
        }
        float corr1 = __expf(m1 - nm1);
        float corr2 = __expf(m2 - nm2);
        m1 = nm1; m2 = nm2;
        float rs1 = 0.0f, rs2 = 0.0f;
        #pragma unroll
        for (int nt = 0; nt < 8; nt++) {
            sc[nt][0] = __expf(sc[nt][0] - m1);
            sc[nt][1] = __expf(sc[nt][1] - m1);
            sc[nt][2] = __expf(sc[nt][2] - m2);
            sc[nt][3] = __expf(sc[nt][3] - m2);
            rs1 += sc[nt][0] + sc[nt][1];
            rs2 += sc[nt][2] + sc[nt][3];
        }
        #pragma unroll
        for (int o = 1; o <= 2; o <<= 1) {
            rs1 += __shfl_xor_sync(0xffffffff, rs1, o);
            rs2 += __shfl_xor_sync(0xffffffff, rs2, o);
        }
        l1 = l1 * corr1 + rs1;
        l2 = l2 * corr2 + rs2;
        #pragma unroll
        for (int dt = 0; dt < 8; dt++) {
            oacc[dt][0] *= corr1; oacc[dt][1] *= corr1;
            oacc[dt][2] *= corr2; oacc[dt][3] *= corr2;
        }

        #pragma unroll
        for (int ks = 0; ks < 4; ks++) {
            uint32_t pa[4];
            pa[0] = packh2(sc[2 * ks][0],     sc[2 * ks][1]);
            pa[1] = packh2(sc[2 * ks][2],     sc[2 * ks][3]);
            pa[2] = packh2(sc[2 * ks + 1][0], sc[2 * ks + 1][1]);
            pa[3] = packh2(sc[2 * ks + 1][2], sc[2 * ks + 1][3]);
            #pragma unroll
            for (int dt = 0; dt < 8; dt++) {
                int kt = ks * 16 + (lane & 15);
                uint32_t vb[2];
                ldsm_x2t(vb, vB + (uint32_t)(kt * 128 + ((dt ^ (kt & 7)) << 4)));
                mma_f16(oacc[dt], pa, vb);
            }
        }
    }

    float inv1 = 1.0f / l1, inv2 = 1.0f / l2;
    int rowg = b * T_ + q0 + r1loc;
    #pragma unroll
    for (int dt = 0; dt < 8; dt++) {
        int col = h * D_ + dt * 8 + (lane & 3) * 2;
        *(__half2*)(o16 + (size_t)rowg * C_ + col) =
            __floats2half2_rn(oacc[dt][0] * inv1, oacc[dt][1] * inv1);
        *(__half2*)(o16 + (size_t)(rowg + 8) * C_ + col) =
            __floats2half2_rn(oacc[dt][2] * inv2, oacc[dt][3] * inv2);
    }
}

// ================= fp16 GEMM: C = A*(Bh[+Bl]), 2 CTAs/SM =================
// Tile 128x128, BK=64, 256 threads.
// TERMS==1: 3-stage (3x32KB=96KB), single-sync loop.
// TERMS==2: 2-stage (2x48KB=96KB), double-sync loop.
template<int HAS_BIAS, int DO_GELU, int DO_RES, int WRITE_F16, int TERMS>
__global__ __launch_bounds__(256, 2) void tc_gemm(
        const __half* __restrict__ Af,
        const __half* __restrict__ Bhi, const __half* __restrict__ Blo,
        const float* __restrict__ bias, const float* __restrict__ res,
        float* __restrict__ Cf, __half* __restrict__ C16,
        int M, int Nb, int Nc, int K) {
    constexpr int STAGES = (TERMS == 2) ? 2 : 3;
    constexpr uint32_t STGB = (TERMS == 2) ? 49152u : 32768u;
    extern __shared__ __align__(1024) char dsm[];
    uint32_t sb = smem_u32(dsm);
    const int tid = threadIdx.x, lane = tid & 31, wid = tid >> 5;
    const int wm = wid >> 2, wn = wid & 3;
    const int m0 = blockIdx.x * 128, n0 = blockIdx.y * 128;
    const int niter = K >> 6;

    float acc[4][4][4];
    #pragma unroll
    for (int a = 0; a < 4; a++)
        #pragma unroll
        for (int b = 0; b < 4; b++)
            #pragma unroll
            for (int c = 0; c < 4; c++) acc[a][b][c] = 0.0f;

    auto PREFETCH = [&](int it) {
        if (it < niter) {
            int k0 = it << 6;
            uint32_t buf = sb + (it % STAGES) * STGB;
            #pragma unroll
            for (int i = 0; i < 4; i++) {
                int e = tid + 256 * i;
                int r = e >> 3, u = e & 7;
                uint32_t d = buf + (uint32_t)(r * 128 + ((u ^ (r & 7)) << 4));
                cp16(d, Af + (size_t)(m0 + r) * K + k0 + u * 8);
            }
            #pragma unroll
            for (int i = 0; i < 4; i++) {
                int e = tid + 256 * i;
                int kr = e >> 4, u = e & 15;
                uint32_t d = buf + 16384 + (uint32_t)(kr * 256 + ((u ^ (kr & 7)) << 4));
                size_t so = (size_t)(k0 + kr) * Nb + n0 + u * 8;
                cp16(d, Bhi + so);
                if (TERMS == 2) cp16(d + 16384, Blo + so);
            }
        }
        cp_commit();
    };

    auto COMPUTE = [&](int stg) {
        uint32_t aBase = sb + stg * STGB;
        uint32_t bBase = aBase + 16384;
        #pragma unroll
        for (int ks = 0; ks < 4; ks++) {
            uint32_t af[4][4];
            #pragma unroll
            for (int mt = 0; mt < 4; mt++) {
                int r = wm * 64 + mt * 16 + (lane & 15);
                int c = ks * 2 + (lane >> 4);
                uint32_t off = (uint32_t)(r * 128 + ((c ^ (r & 7)) << 4));
                ldsm_x4(af[mt], aBase + off);
            }
            uint32_t bh[4][2], blr[4][2];
            #pragma unroll
            for (int nt = 0; nt < 4; nt++) {
                int kt = ks * 16 + (lane & 15);
                int c = wn * 4 + nt;
                uint32_t off = (uint32_t)(kt * 256 + ((c ^ (kt & 7)) << 4));
                ldsm_x2t(bh[nt],  bBase + off);
                if (TERMS == 2) ldsm_x2t(blr[nt], bBase + 16384 + off);
            }
            #pragma unroll
            for (int mt = 0; mt < 4; mt++)
                #pragma unroll
                for (int nt = 0; nt < 4; nt++) {
                    mma_f16(acc[mt][nt], af[mt], bh[nt]);
                    if (TERMS == 2) mma_f16(acc[mt][nt], af[mt], blr[nt]);
                }
        }
    };

    if (TERMS == 1) {
        // 3-stage, one sync per iter
        PREFETCH(0);
        PREFETCH(1);
        for (int it = 0; it < niter; it++) {
            asm volatile("cp.async.wait_group 1;" ::: "memory");
            __syncthreads();
            COMPUTE(it % STAGES);
            PREFETCH(it + 2);
        }
    } else {
        // 2-stage, two syncs per iter
        PREFETCH(0);
        for (int it = 0; it < niter; it++) {
            PREFETCH(it + 1);
            asm volatile("cp.async.wait_group 1;" ::: "memory");
            __syncthreads();
            COMPUTE(it % STAGES);
            __syncthreads();
        }
    }

    #pragma unroll
    for (int mt = 0; mt < 4; mt++) {
        int r0 = m0 + wm * 64 + mt * 16 + (lane >> 2);
        #pragma unroll
        for (int nt = 0; nt < 4; nt++) {
            int c0 = n0 + wn * 32 + nt * 8 + (lane & 3) * 2;
            float v[4];
            #pragma unroll
            for (int i = 0; i < 4; i++) {
                v[i] = acc[mt][nt][i];
                int col = c0 + (i & 1);
                if (HAS_BIAS && col < Nc) v[i] += bias[col];
                if (DO_GELU) v[i] = gelu_exact(v[i]);
            }
            if (WRITE_F16) {
                #pragma unroll
                for (int half_i = 0; half_i < 2; half_i++) {
                    int row = r0 + half_i * 8;
                    size_t o = (size_t)row * Nc + c0;
                    *(__half2*)(C16 + o) =
                        __floats2half2_rn(v[half_i * 2], v[half_i * 2 + 1]);
                }
            } else {
                #pragma unroll
                for (int i = 0; i < 4; i++) {
                    int row = r0 + (i >> 1) * 8;
                    int col = c0 + (i & 1);
                    if (col < Nc) {
                        float w = v[i];
                        if (DO_RES) w += res[(size_t)row * Nc + col];
                        Cf[(size_t)row * Nc + col] = w;
                    }
                }
            }
        }
    }
}

#define GEMM_SMEM 98304   // both variants: 3x32KB or 2x48KB

// ---------------- launch ----------------
extern "C" void kernel_launch(void* const* d_in, const int* in_sizes, int n_in,
                              void* d_out, int out_size) {
    const int*   idx    = (const int*)  d_in[0];
    const float* wte    = (const float*)d_in[1];
    const float* pte    = (const float*)d_in[2];
    const float* ln1_s  = (const float*)d_in[3];
    const float* ln1_b  = (const float*)d_in[4];
    const float* qkv_w  = (const float*)d_in[5];
    const float* qkv_b  = (const float*)d_in[6];
    const float* proj_w = (const float*)d_in[7];
    const float* proj_b = (const float*)d_in[8];
    const float* ln2_s  = (const float*)d_in[9];
    const float* ln2_b  = (const float*)d_in[10];
    const float* w1     = (const float*)d_in[11];
    const float* b1     = (const float*)d_in[12];
    const float* w2     = (const float*)d_in[13];
    const float* b2     = (const float*)d_in[14];
    const float* lnf_s  = (const float*)d_in[15];
    const float* lnf_b  = (const float*)d_in[16];
    const float* head_w = (const float*)d_in[17];
    float* out = (float*)d_out;

    float* px;
    cudaGetSymbolAddress((void**)&px, g_x);
    __half *qkv16, *ln16, *att16, *mid16;
    cudaGetSymbolAddress((void**)&qkv16, g_qkv16);
    cudaGetSymbolAddress((void**)&ln16,  g_ln16);
    cudaGetSymbolAddress((void**)&att16, g_att16);
    cudaGetSymbolAddress((void**)&mid16, g_mid16);
    __half *qwh, *pwh, *pwl, *w1h, *w2h, *w2l, *hwh;
    cudaGetSymbolAddress((void**)&qwh, g_qkvw_h);
    cudaGetSymbolAddress((void**)&pwh, g_projw_h); cudaGetSymbolAddress((void**)&pwl, g_projw_l);
    cudaGetSymbolAddress((void**)&w1h, g_w1_h);
    cudaGetSymbolAddress((void**)&w2h, g_w2_h);   cudaGetSymbolAddress((void**)&w2l, g_w2_l);
    cudaGetSymbolAddress((void**)&hwh, g_hw_h);

    cudaFuncSetAttribute(tc_gemm<1,0,0,1,1>, cudaFuncAttributeMaxDynamicSharedMemorySize, GEMM_SMEM);
    cudaFuncSetAttribute(tc_gemm<1,0,1,0,2>, cudaFuncAttributeMaxDynamicSharedMemorySize, GEMM_SMEM);
    cudaFuncSetAttribute(tc_gemm<1,1,0,1,1>, cudaFuncAttributeMaxDynamicSharedMemorySize, GEMM_SMEM);
    cudaFuncSetAttribute(tc_gemm<0,0,0,0,1>, cudaFuncAttributeMaxDynamicSharedMemorySize, GEMM_SMEM);

    // ---- weight conversion (once per replay) ----
    {
        int n;
        n = L_ * C_ * 3 * C_ / 4;
        convert_hi_kernel<<<(n + 255) / 256, 256>>>(qkv_w, qwh, n);
        n = L_ * C_ * C_ / 4;
        convert_kernel<<<(n + 255) / 256, 256>>>(proj_w, pwh, pwl, n);
        n = L_ * C_ * F_ / 4;
        convert_hi_kernel<<<(n + 255) / 256, 256>>>(w1, w1h, n);
        n = L_ * F_ * C_ / 4;
        convert_kernel<<<(n + 255) / 256, 256>>>(w2, w2h, w2l, n);
        n = C_ * VP_ / 4;
        convert_head_kernel<<<(n + 255) / 256, 256>>>(head_w, hwh);
    }

    embed_kernel<<<M_, 256>>>(idx, wte, pte, px);

    for (int l = 0; l < L_; l++) {
        const __half* qwh_l = qwh + (size_t)l * C_ * 3 * C_;
        const __half* pwh_l = pwh + (size_t)l * C_ * C_;
        const __half* pwl_l = pwl + (size_t)l * C_ * C_;
        const __half* w1h_l = w1h + (size_t)l * C_ * F_;
        const __half* w2h_l = w2h + (size_t)l * F_ * C_;
        const __half* w2l_l = w2l + (size_t)l * F_ * C_;

        layernorm_kernel<<<M_ / 8, 256>>>(px, ln1_s + (size_t)l * C_, ln1_b + (size_t)l * C_, ln16);

        // qkv = ln @ qkv_w + qkv_b  -> fp16, 1-term (softmax-shielded)
        tc_gemm<1,0,0,1,1><<<dim3(M_ / 128, 3 * C_ / 128), 256, GEMM_SMEM>>>(
            ln16, qwh_l, nullptr, qkv_b + (size_t)l * 3 * C_, nullptr,
            nullptr, qkv16, M_, 3 * C_, 3 * C_, C_);

        attn_kernel<<<dim3(T_ / 64, B_ * H_), 128>>>(qkv16, att16);

        // x = x + att @ proj_w + proj_b   (2-term: residual writer)
        tc_gemm<1,0,1,0,2><<<dim3(M_ / 128, C_ / 128), 256, GEMM_SMEM>>>(
            att16, pwh_l, pwl_l, proj_b + (size_t)l * C_, px,
            px, nullptr, M_, C_, C_, C_);

        layernorm_kernel<<<M_ / 8, 256>>>(px, ln2_s + (size_t)l * C_, ln2_b + (size_t)l * C_, ln16);

        // mid = gelu(ln2 @ w1 + b1) -> fp16, 1-term (GELU-shielded)
        tc_gemm<1,1,0,1,1><<<dim3(M_ / 128, F_ / 128), 256, GEMM_SMEM>>>(
            ln16, w1h_l, nullptr, b1 + (size_t)l * F_, nullptr,
            nullptr, mid16, M_, F_, F_, C_);

        // x = x + mid @ w2 + b2   (2-term: residual writer)
        tc_gemm<1,0,1,0,2><<<dim3(M_ / 128, C_ / 128), 256, GEMM_SMEM>>>(
            mid16, w2h_l, w2l_l, b2 + (size_t)l * C_, px,
            px, nullptr, M_, C_, C_, F_);
    }

    layernorm_kernel<<<M_ / 8, 256>>>(px, lnf_s, lnf_b, ln16);

    // logits = lnf @ head_w, single fp16 term, N padded to 50304
    tc_gemm<0,0,0,0,1><<<dim3(M_ / 128, VP_ / 128), 256, GEMM_SMEM>>>(
        ln16, hwh, nullptr, nullptr, nullptr,
        out, nullptr, M_, VP_, V_, C_);
}